// round 7
// baseline (speedup 1.0000x reference)
#include <cuda_runtime.h>

// RoI max pooling, channel-resident-in-SMEM formulation.
//   x: (1,256,64,64) f32   rois: (1,512,4) i32 (rx,ry,rw,rh)   out: (512,256,7,7) f32
// dh = rh/7, dw = rw/7 in [1,4]; clipping in the reference is provably inactive
// (ry<=35, dh*6+t<=27 -> row<=62; same for cols), and dh,dw>=1 so masks always
// admit (0,0).
//
// Block = (channel c, quarter of rois). Loads the 16KB channel into smem once
// (rows padded to 65 floats: bank=(row+col)%32, killing same-column conflicts),
// then each thread owns one output bin kj for 5 roi-streams and gathers purely
// from smem. Converts all ~28M gather reads from L2-latency LDG (the round 2-4
// bottleneck: latency-bound, no pipe saturated) into cheap LDS.

#define OUTC   49
#define SPLIT  4
#define RPB    (512 / SPLIT)      // 128 rois per block
#define THREADS 256

__global__ void __launch_bounds__(THREADS) roipool_smem(
    const float* __restrict__ x,
    const int4*  __restrict__ rois,
    float*       __restrict__ out)
{
    __shared__ float sx[64][65];          // padded: bank = (row + col) % 32
    __shared__ int4  sroi[RPB];

    const int c     = blockIdx.x & 255;   // channel
    const int quart = blockIdx.x >> 8;    // 0..3
    const int tid   = threadIdx.x;
    const int nbase = quart * RPB;

    // Load channel c into smem: 1024 float4, fully coalesced.
    const float4* xc = (const float4*)(x + c * 4096);
    #pragma unroll
    for (int i = tid; i < 1024; i += THREADS) {
        float4 v = __ldg(xc + i);
        const int row = i >> 4;
        const int col = (i & 15) << 2;
        sx[row][col]     = v.x;
        sx[row][col + 1] = v.y;
        sx[row][col + 2] = v.z;
        sx[row][col + 3] = v.w;
    }
    // Load this block's roi slice (128 int4, coalesced).
    if (tid < RPB) sroi[tid] = __ldg(rois + nbase + tid);
    __syncthreads();

    if (tid >= 5 * OUTC) return;          // 245 workers
    const int kj = tid % OUTC;            // fixed output bin for this thread
    const int rg = tid / OUTC;            // roi stream 0..4
    const int k  = kj / 7;
    const int j  = kj % 7;

    float* ob = out + (size_t)nbase * (256 * OUTC) + c * OUTC + kj;

    #pragma unroll 1
    for (int roi = rg; roi < RPB; roi += 5) {
        const int4 r  = sroi[roi];
        const int  dh = r.w / 7;          // 1..4 (const-div -> mul/shift)
        const int  dw = r.z / 7;
        const int  row0 = r.y + dh * k;
        const int  col0 = r.x + dw * j;

        float m = sx[row0][col0];
        #pragma unroll 1
        for (int t = 0; t < dh; ++t) {
            const float* sr = &sx[row0 + t][col0];
            #pragma unroll 1
            for (int s = 0; s < dw; ++s)
                m = fmaxf(m, sr[s]);
        }
        ob[roi * (256 * OUTC)] = m;
    }
}

extern "C" void kernel_launch(void* const* d_in, const int* in_sizes, int n_in,
                              void* d_out, int out_size)
{
    const float* x    = (const float*)d_in[0];
    const int4*  rois = (const int4*) d_in[1];
    float*       out  = (float*)d_out;

    roipool_smem<<<256 * SPLIT, THREADS>>>(x, rois, out);  // 1024 blocks
}

// round 13
// speedup vs baseline: 1.2782x; 1.2782x over previous
#include <cuda_runtime.h>

// RoI max pooling: channel-in-SMEM + compile-time (dh,dw) specialization.
//   x: (1,256,64,64) f32   rois: (1,512,4) i32 (rx,ry,rw,rh)   out: (512,256,7,7) f32
// dh=rh/7, dw=rw/7 in [1,4]; reference clipping provably inactive; dh,dw>=1.
//
// R7 post-mortem: gather now hits SMEM (L2=13%) but kernel is issue-bound
// (~20M warp-instr from dynamic dh/dw loops). Fix: 16-way switch on (dh,dw)
// -> fully unrolled immediate-offset LDS bodies; threads in 4 groups of 64
// (kj = tid&63, active<49) so every warp holds ONE roi -> uniform dispatch;
// dh/dw divisions hoisted into the staging phase; store pointer strength-
// reduced. ~7M warp-instr expected.

#define OUTC    49
#define SPLIT   4
#define RPB     (512 / SPLIT)     // 128 rois per block
#define THREADS 256
#define PITCH   65                // smem row pitch: bank = (row+col) % 32

__device__ __forceinline__ float wmax(float a, float b) { return fmaxf(a, b); }

template<int DH, int DW>
__device__ __forceinline__ float winmax(const float* __restrict__ b) {
    float v[DH * DW];
    #pragma unroll
    for (int t = 0; t < DH; ++t)
        #pragma unroll
        for (int s = 0; s < DW; ++s)
            v[t * DW + s] = b[t * PITCH + s];   // immediate offsets, loads batched
    float m = v[0];
    #pragma unroll
    for (int i = 1; i < DH * DW; ++i) m = wmax(m, v[i]);
    return m;
}

__global__ void __launch_bounds__(THREADS) roipool_v8(
    const float* __restrict__ x,
    const int4*  __restrict__ rois,
    float*       __restrict__ out)
{
    __shared__ float sx[64][PITCH];
    __shared__ int4  sroi[RPB];               // {rx, ry, dw, dh}

    const int c     = blockIdx.x & 255;
    const int quart = blockIdx.x >> 8;
    const int tid   = threadIdx.x;
    const int nbase = quart * RPB;

    // Stage channel c (16 KB, coalesced float4).
    const float4* xc = (const float4*)(x + c * 4096);
    #pragma unroll
    for (int i = tid; i < 1024; i += THREADS) {
        float4 v = __ldg(xc + i);
        const int row = i >> 4;
        const int col = (i & 15) << 2;
        sx[row][col] = v.x;  sx[row][col+1] = v.y;
        sx[row][col+2] = v.z; sx[row][col+3] = v.w;
    }
    // Stage rois with dh/dw pre-divided.
    if (tid < RPB) {
        int4 r = __ldg(rois + nbase + tid);
        sroi[tid] = make_int4(r.x, r.y, r.z / 7, r.w / 7);
    }
    __syncthreads();

    // 4 groups of 64 threads; kj = tid&63 (49 active) -> warps never mix rois.
    const int g  = tid >> 6;                  // roi stream 0..3
    const int kj = tid & 63;
    if (kj >= OUTC) return;
    const int k = kj / 7;
    const int j = kj % 7;

    float* op = out + (nbase + g) * (256 * OUTC) + c * OUTC + kj;
    const int OSTRIDE = 4 * 256 * OUTC;       // 4 rois ahead per iter

    #pragma unroll 1
    for (int i = g; i < RPB; i += 4, op += OSTRIDE) {
        const int4 r = sroi[i];               // broadcast LDS.128
        float m;
        #define CASE(DH, DW) \
          case ((DH - 1) * 4 + (DW - 1)): \
            m = winmax<DH, DW>(&sx[r.y + DH * k][r.x + DW * j]); break;
        switch (((r.w - 1) << 2) | (r.z - 1)) {
            CASE(1,1) CASE(1,2) CASE(1,3) CASE(1,4)
            CASE(2,1) CASE(2,2) CASE(2,3) CASE(2,4)
            CASE(3,1) CASE(3,2) CASE(3,3) CASE(3,4)
            CASE(4,1) CASE(4,2) CASE(4,3) CASE(4,4)
            default: m = 0.0f; break;         // unreachable
        }
        #undef CASE
        *op = m;
    }
}

extern "C" void kernel_launch(void* const* d_in, const int* in_sizes, int n_in,
                              void* d_out, int out_size)
{
    const float* x    = (const float*)d_in[0];
    const int4*  rois = (const int4*) d_in[1];
    float*       out  = (float*)d_out;

    roipool_v8<<<256 * SPLIT, THREADS>>>(x, rois, out);  // 1024 blocks
}

// round 14
// speedup vs baseline: 1.2853x; 1.0056x over previous
#include <cuda_runtime.h>

// RoI max pooling: 2-channels-in-SMEM + compile-time (dh,dw) windows + roi prefetch.
//   x: (1,256,64,64) f32   rois: (1,512,4) i32 (rx,ry,rw,rh)   out: (512,256,7,7) f32
// dh=rh/7, dw=rw/7 in [1,4]; reference clipping provably inactive; dh,dw>=1.
//
// v8 measured 21.1us, issue-bound-ish (issue 54%, ~12M warp-instr): per-roi
// overhead (roi LDS -> dispatch -> addressing -> store) is ~half the stream and
// a ~100cyc serial chain. v9: (a) block stages TWO adjacent channels (one
// coalesced 32KB load; channels contiguous in x) so roi record + dispatch +
// base address amortize over 2 outputs, second channel = same offset +
// compile-time CH_STRIDE immediate, 2 independent LDS chains (MLP); (b) roi
// record prefetched one iteration ahead ((i+4)&63 wrap, branchless) so the roi
// LDS latency is off the critical path.

#define OUTC     49
#define SPLIT    8
#define RPB      (512 / SPLIT)    // 64 rois per block
#define THREADS  256
#define PITCH    65               // bank = (row + col) % 32
#define CH_STRIDE (64 * PITCH)    // 4160 floats between channel planes

template<int DH, int DW>
__device__ __forceinline__ void winmax2(const float* __restrict__ b,
                                        float& m0, float& m1) {
    float v0[DH * DW], v1[DH * DW];
    #pragma unroll
    for (int t = 0; t < DH; ++t)
        #pragma unroll
        for (int s = 0; s < DW; ++s) {
            v0[t * DW + s] = b[t * PITCH + s];              // immediate offsets
            v1[t * DW + s] = b[CH_STRIDE + t * PITCH + s];  // second channel
        }
    float a = v0[0], c = v1[0];
    #pragma unroll
    for (int i = 1; i < DH * DW; ++i) { a = fmaxf(a, v0[i]); c = fmaxf(c, v1[i]); }
    m0 = a; m1 = c;
}

__global__ void __launch_bounds__(THREADS) roipool_v9(
    const float* __restrict__ x,
    const int4*  __restrict__ rois,
    float*       __restrict__ out)
{
    __shared__ float sx[2 * 64 * PITCH];      // 33,280 B
    __shared__ int4  sroi[RPB];               // {rx, ry, dw, dh}

    const int cp    = blockIdx.x & 127;       // channel pair -> c0 = 2*cp
    const int quart = blockIdx.x >> 7;        // 0..7
    const int tid   = threadIdx.x;
    const int nbase = quart * RPB;
    const int c0    = cp << 1;

    // Stage channels c0, c0+1 (contiguous 32KB in x): 2048 float4, coalesced.
    const float4* xc = (const float4*)(x + c0 * 4096);
    #pragma unroll
    for (int i = tid; i < 2048; i += THREADS) {
        float4 v = __ldg(xc + i);
        const int ch  = i >> 10;
        const int row = (i >> 4) & 63;
        const int col = (i & 15) << 2;
        float* d = sx + ch * CH_STRIDE + row * PITCH + col;
        d[0] = v.x; d[1] = v.y; d[2] = v.z; d[3] = v.w;
    }
    // Stage rois with dh/dw pre-divided.
    if (tid < RPB) {
        int4 r = __ldg(rois + nbase + tid);
        sroi[tid] = make_int4(r.x, r.y, r.z / 7, r.w / 7);
    }
    __syncthreads();

    // 4 groups of 64; kj = tid&63 (49 active) -> warps never mix rois.
    const int g  = tid >> 6;
    const int kj = tid & 63;
    if (kj >= OUTC) return;
    const int k = kj / 7;
    const int j = kj % 7;

    float* op = out + (nbase + g) * (256 * OUTC) + c0 * OUTC + kj;
    const int OSTRIDE = 4 * 256 * OUTC;

    int4 r = sroi[g];                          // first roi, prefetched
    #pragma unroll 1
    for (int i = g; i < RPB; i += 4, op += OSTRIDE) {
        const int4 rn = sroi[(i + 4) & (RPB - 1)];   // branchless prefetch
        float m0, m1;
        #define CASE(DH, DW) \
          case ((DH - 1) * 4 + (DW - 1)): \
            winmax2<DH, DW>(sx + (r.y + DH * k) * PITCH + (r.x + DW * j), m0, m1); break;
        switch (((r.w - 1) << 2) | (r.z - 1)) {
            CASE(1,1) CASE(1,2) CASE(1,3) CASE(1,4)
            CASE(2,1) CASE(2,2) CASE(2,3) CASE(2,4)
            CASE(3,1) CASE(3,2) CASE(3,3) CASE(3,4)
            CASE(4,1) CASE(4,2) CASE(4,3) CASE(4,4)
            default: m0 = m1 = 0.0f; break;    // unreachable
        }
        #undef CASE
        op[0]    = m0;                         // channel c0   (coalesced)
        op[OUTC] = m1;                         // channel c0+1 (coalesced)
        r = rn;
    }
}

extern "C" void kernel_launch(void* const* d_in, const int* in_sizes, int n_in,
                              void* d_out, int out_size)
{
    const float* x    = (const float*)d_in[0];
    const int4*  rois = (const int4*) d_in[1];
    float*       out  = (float*)d_out;

    roipool_v9<<<128 * SPLIT, THREADS>>>(x, rois, out);   // 1024 blocks
}